// round 17
// baseline (speedup 1.0000x reference)
#include <cuda_runtime.h>
#include <cstdint>
#include <mma.h>

using namespace nvcuda;

#define N_NODES 50000
#define CH 64

// sum-only accumulator (zeroed by memset node; x added during GEMM staging)
__device__ float4 g_agg4[N_NODES * (CH / 4)];

// ---------------------------------------------------------------------------
// Kernel 1: scatter-add. 8-lane group per edge; lane owns float4 j and j+8.
// (MLP=2 — proven optimum; at the LTS traffic floor)
// Edge-index dtype detected INLINE per warp (1 hot LDG + ballot).
// ---------------------------------------------------------------------------
__global__ void scatter_kernel(const float4* __restrict__ x4,
                               const void* __restrict__ ei_raw,
                               int nE) {
    const int* ei32 = (const int*)ei_raw;
    int wlane = threadIdx.x & 31;
    int bad = (ei32[2 * wlane + 1] != 0);
    unsigned m = __ballot_sync(0xFFFFFFFFu, bad);
    bool is64 = (m == 0u);

    int g = blockIdx.x * blockDim.x + threadIdx.x;
    int lane = g & 7;
    int edge = g >> 3;
    if (edge >= nE) return;

    long long src, dst;
    if (is64) {
        const long long* ei = (const long long*)ei_raw;
        src = ei[edge];
        dst = ei[nE + edge];
    } else {
        src = ei32[edge];
        dst = ei32[nE + edge];
    }
    if ((unsigned long long)src >= N_NODES || (unsigned long long)dst >= N_NODES)
        return;

    float4 v0 = x4[src * 16 + lane];
    float4 v1 = x4[src * 16 + lane + 8];
    float4* d0 = g_agg4 + dst * 16 + lane;
    float4* d1 = g_agg4 + dst * 16 + lane + 8;
    asm volatile("red.global.add.v4.f32 [%0], {%1, %2, %3, %4};"
                 :: "l"(d0), "f"(v0.x), "f"(v0.y), "f"(v0.z), "f"(v0.w)
                 : "memory");
    asm volatile("red.global.add.v4.f32 [%0], {%1, %2, %3, %4};"
                 :: "l"(d1), "f"(v1.x), "f"(v1.y), "f"(v1.z), "f"(v1.w)
                 : "memory");
}

// ---------------------------------------------------------------------------
// Kernel 2: out = relu((x + agg) @ W^T + b) via WMMA tf32 with 3-term split:
//   C = Ahi*Bhi + Ahi*Blo + Alo*Bhi   (lo = v - tf32(v); omitted Alo*Blo
//   term is ~2^-22 relative -> fp32-grade accuracy).
// GROWS=64 rows/block, 256 threads (8 warps), 16 warp-tiles of 16x16,
// 2 tiles/warp, k-loop of 8 steps of k=8.
// ---------------------------------------------------------------------------
#define GROWS 64
#define GTHREADS 256
#define A_LD 72
#define B_LD 72
#define C_LD 20
#define OFF_AHI 0
#define OFF_ALO (GROWS * A_LD)
#define OFF_BHI (2 * GROWS * A_LD)
#define OFF_BLO (2 * GROWS * A_LD + 64 * B_LD)
#define OFF_C   (2 * GROWS * A_LD + 2 * 64 * B_LD)
#define SMEM_FLOATS (OFF_C + 8 * 16 * C_LD)
#define SMEM_BYTES (SMEM_FLOATS * 4)

__device__ __forceinline__ float tf32_rn(float v) {
    uint32_t u;
    asm("cvt.rna.tf32.f32 %0, %1;" : "=r"(u) : "f"(v));
    return __uint_as_float(u);
}

__global__ void __launch_bounds__(GTHREADS) gemm_relu_kernel(
    const float4* __restrict__ x4,
    const float* __restrict__ W,   // [64,64] row-major (o,i)
    const float* __restrict__ b,   // [64]
    float* __restrict__ out)       // [N,64]
{
    extern __shared__ float sm[];

    int t = threadIdx.x;
    int r0 = blockIdx.x * GROWS;

    // Stage B = W^T (B[k][n] = W[n][k]), split hi/lo: 4096 / 256 = 16 each
    #pragma unroll
    for (int k = 0; k < 16; k++) {
        int idx = t + k * 256;       // idx = n*64 + kk
        int n = idx >> 6;
        int kk = idx & 63;
        float v = W[idx];
        float hi = tf32_rn(v);
        float lo = tf32_rn(v - hi);
        sm[OFF_BHI + kk * B_LD + n] = hi;
        sm[OFF_BLO + kk * B_LD + n] = lo;
    }
    // Stage A = x + agg, split hi/lo, coalesced: 1024 f4 / 256 = 4 each
    #pragma unroll
    for (int k = 0; k < 4; k++) {
        int idx = t + k * 256;
        int row = idx >> 4;          // 0..63
        int c4  = idx & 15;
        int grow = r0 + row;
        float4 v = make_float4(0.f, 0.f, 0.f, 0.f);
        if (grow < N_NODES) {
            float4 vx = x4[grow * 16 + c4];
            float4 va = g_agg4[grow * 16 + c4];
            v = make_float4(vx.x + va.x, vx.y + va.y, vx.z + va.z, vx.w + va.w);
        }
        float4 hi, lo;
        hi.x = tf32_rn(v.x); lo.x = tf32_rn(v.x - hi.x);
        hi.y = tf32_rn(v.y); lo.y = tf32_rn(v.y - hi.y);
        hi.z = tf32_rn(v.z); lo.z = tf32_rn(v.z - hi.z);
        hi.w = tf32_rn(v.w); lo.w = tf32_rn(v.w - hi.w);
        *reinterpret_cast<float4*>(&sm[OFF_AHI + row * A_LD + c4 * 4]) = hi;
        *reinterpret_cast<float4*>(&sm[OFF_ALO + row * A_LD + c4 * 4]) = lo;
    }
    __syncthreads();

    int w = t >> 5;
    int lane = t & 31;
    float* scratch = &sm[OFF_C + w * 16 * C_LD];

    // 16 tiles (4 row x 4 col); warp w does tiles w and w+8
    #pragma unroll
    for (int ti = w; ti < 16; ti += 8) {
        int tile_r = ti >> 2;
        int tile_c = ti & 3;
        int row0 = tile_r * 16;
        int col0 = tile_c * 16;

        wmma::fragment<wmma::accumulator, 16, 16, 8, float> c;
        wmma::fill_fragment(c, 0.0f);

        #pragma unroll
        for (int k0 = 0; k0 < 8; k0++) {
            wmma::fragment<wmma::matrix_a, 16, 16, 8, wmma::precision::tf32, wmma::row_major> ahi, alo;
            wmma::fragment<wmma::matrix_b, 16, 16, 8, wmma::precision::tf32, wmma::row_major> bhi, blo;
            wmma::load_matrix_sync(ahi, &sm[OFF_AHI + row0 * A_LD + k0 * 8], A_LD);
            wmma::load_matrix_sync(alo, &sm[OFF_ALO + row0 * A_LD + k0 * 8], A_LD);
            wmma::load_matrix_sync(bhi, &sm[OFF_BHI + (k0 * 8) * B_LD + col0], B_LD);
            wmma::load_matrix_sync(blo, &sm[OFF_BLO + (k0 * 8) * B_LD + col0], B_LD);
            wmma::mma_sync(c, ahi, bhi, c);
            wmma::mma_sync(c, ahi, blo, c);
            wmma::mma_sync(c, alo, bhi, c);
        }

        wmma::store_matrix_sync(scratch, c, C_LD, wmma::mem_row_major);
        __syncwarp();

        #pragma unroll
        for (int j = 0; j < 8; j++) {
            int e = lane + j * 32;           // 0..255
            int row = e >> 4;
            int col = e & 15;
            int grow = r0 + row0 + row;
            if (grow < N_NODES) {
                float v = scratch[row * C_LD + col] + b[col0 + col];
                out[grow * CH + col0 + col] = fmaxf(v, 0.f);
            }
        }
        __syncwarp();
    }
}

// ---------------------------------------------------------------------------
extern "C" void kernel_launch(void* const* d_in, const int* in_sizes, int n_in,
                              void* d_out, int out_size) {
    const float* x  = (const float*)d_in[0];
    const void*  ei = d_in[1];
    const float* W  = (const float*)d_in[2];
    const float* b  = (const float*)d_in[3];
    float* out = (float*)d_out;

    int nE = in_sizes[1] / 2;                 // 800000

    static bool attr_done = false;
    static void* agg_ptr = nullptr;
    if (!attr_done) {
        cudaFuncSetAttribute(gemm_relu_kernel,
                             cudaFuncAttributeMaxDynamicSharedMemorySize,
                             SMEM_BYTES);
        cudaGetSymbolAddress(&agg_ptr, g_agg4);
        attr_done = true;
    }

    cudaMemsetAsync(agg_ptr, 0, sizeof(float4) * N_NODES * (CH / 4));

    long long threads = (long long)nE * 8;
    int blocks = (int)((threads + 255) / 256);
    scatter_kernel<<<blocks, 256>>>(
        reinterpret_cast<const float4*>(x), ei, nE);

    int gblocks = (N_NODES + GROWS - 1) / GROWS;
    gemm_relu_kernel<<<gblocks, GTHREADS, SMEM_BYTES>>>(
        reinterpret_cast<const float4*>(x), W, b, out);
}